// round 1
// baseline (speedup 1.0000x reference)
#include <cuda_runtime.h>
#include <math.h>

#define NB      2048
#define NENT    8256
#define NCOMP   128
#define KAPPA   0.276f

__device__ float g_rn[NB];

// ---------- complex helpers (float2 = re, im) ----------
__device__ __forceinline__ float2 cmul(float2 a, float2 b) {
    return make_float2(a.x * b.x - a.y * b.y, a.x * b.y + a.y * b.x);
}
__device__ __forceinline__ float2 cadd(float2 a, float2 b) {
    return make_float2(a.x + b.x, a.y + b.y);
}
__device__ __forceinline__ float2 csub(float2 a, float2 b) {
    return make_float2(a.x - b.x, a.y - b.y);
}
__device__ __forceinline__ float2 cdiv(float2 a, float2 b) {
    float d = b.x * b.x + b.y * b.y;
    float inv = 1.0f / d;
    return make_float2((a.x * b.x + a.y * b.y) * inv,
                       (a.y * b.x - a.x * b.y) * inv);
}

// ---------- w = L * v  (lower-triangular, packed) ----------
// 2 threads per row (column parity h). Warp->row-block remap balances SMSPs.
__device__ __forceinline__ void matvecW(float2* __restrict__ wout,
                                        const float2* __restrict__ vin,
                                        const float2* __restrict__ Ls) {
    int warp = threadIdx.x >> 5, lane = threadIdx.x & 31;
    int blk = (warp < 4) ? warp : (11 - warp);
    int row = blk * 16 + (lane >> 1);
    int h = lane & 1;
    const float2* Lrow = Ls + ((row * (row + 1)) >> 1);
    float2 acc = make_float2(0.f, 0.f);
    for (int c = h; c <= row; c += 2) {
        float2 l = Lrow[c];
        float2 v = vin[c];
        acc.x = fmaf(l.x, v.x, fmaf(-l.y, v.y, acc.x));
        acc.y = fmaf(l.x, v.y, fmaf( l.y, v.x, acc.y));
    }
    acc.x += __shfl_xor_sync(0xffffffffu, acc.x, 1);
    acc.y += __shfl_xor_sync(0xffffffffu, acc.y, 1);
    if (h == 0) wout[row] = acc;
}

// ---------- u = L^H * w  (conj-transpose triangular matvec) ----------
__device__ __forceinline__ void matvecU(float2* __restrict__ uout,
                                        const float2* __restrict__ win,
                                        const float2* __restrict__ Ls) {
    int warp = threadIdx.x >> 5, lane = threadIdx.x & 31;
    int blk = (warp < 4) ? warp : (11 - warp);
    int col = blk * 16 + (lane >> 1);
    int h = lane & 1;
    float2 acc = make_float2(0.f, 0.f);
    int r = col + h;
    int idx = ((r * (r + 1)) >> 1) + col;
    for (; r < 128; r += 2) {
        float2 l = Ls[idx];
        float2 w = win[r];
        acc.x = fmaf(l.x, w.x, fmaf( l.y, w.y, acc.x));
        acc.y = fmaf(l.x, w.y, fmaf(-l.y, w.x, acc.y));
        idx += 2 * r + 3;
    }
    acc.x += __shfl_xor_sync(0xffffffffu, acc.x, 1);
    acc.y += __shfl_xor_sync(0xffffffffu, acc.y, 1);
    if (h == 0) uout[col] = acc;
}

// ---------- Wilson-Dirac stencil: g=+1 -> D, g=-1 -> Ddag ----------
__device__ __forceinline__ void dirac(float2* __restrict__ out,
                                      const float2* __restrict__ in,
                                      const float2* __restrict__ Us,
                                      float g) {
    int t = threadIdx.x;
    if (t < 64) {
        int x = t >> 3, y = t & 7;
        float2 a0 = in[2 * t], a1 = in[2 * t + 1];
        float2 s0 = make_float2(0.f, 0.f), s1 = make_float2(0.f, 0.f);
        // mu = 0 (x direction), G = sigma_x
        {
            int sp = (((x + 1) & 7) << 3) | y;
            int sm = (((x + 7) & 7) << 3) | y;
            float2 u  = Us[t];
            float2 ub = Us[sm]; ub.y = -ub.y;
            float2 f0 = cmul(u,  in[2 * sp]),     f1 = cmul(u,  in[2 * sp + 1]);
            float2 b0 = cmul(ub, in[2 * sm]),     b1 = cmul(ub, in[2 * sm + 1]);
            // (I - g sx) f = (f0 - g f1, f1 - g f0); (I + g sx) b = (b0 + g b1, b1 + g b0)
            s0.x += f0.x - g * f1.x + b0.x + g * b1.x;
            s0.y += f0.y - g * f1.y + b0.y + g * b1.y;
            s1.x += f1.x - g * f0.x + b1.x + g * b0.x;
            s1.y += f1.y - g * f0.y + b1.y + g * b0.y;
        }
        // mu = 1 (y direction), G = sigma_y
        {
            int sp = (x << 3) | ((y + 1) & 7);
            int sm = (x << 3) | ((y + 7) & 7);
            float2 u  = Us[64 + t];
            float2 ub = Us[64 + sm]; ub.y = -ub.y;
            float2 f0 = cmul(u,  in[2 * sp]),     f1 = cmul(u,  in[2 * sp + 1]);
            float2 b0 = cmul(ub, in[2 * sm]),     b1 = cmul(ub, in[2 * sm + 1]);
            // (I - g sy) f = (f0 + g*i*f1, f1 - g*i*f0), i*z = (-z.y, z.x)
            s0.x += f0.x - g * f1.y + b0.x + g * b1.y;
            s0.y += f0.y + g * f1.x + b0.y - g * b1.x;
            s1.x += f1.x + g * f0.y + b1.x - g * b0.y;
            s1.y += f1.y - g * f0.x + b1.y + g * b0.x;
        }
        out[2 * t]     = make_float2(a0.x - KAPPA * s0.x, a0.y - KAPPA * s0.y);
        out[2 * t + 1] = make_float2(a1.x - KAPPA * s1.x, a1.y - KAPPA * s1.y);
    }
}

// ---------- block-wide complex dot: sum conj(a)*c over 128 components ----------
__device__ __forceinline__ float2 dot_all(const float2* __restrict__ a,
                                          const float2* __restrict__ c,
                                          float2* __restrict__ red) {
    int tid = threadIdx.x;
    float2 s = make_float2(0.f, 0.f);
    if (tid < 128) {
        float2 av = a[tid], cv = c[tid];
        s.x = av.x * cv.x + av.y * cv.y;
        s.y = av.x * cv.y - av.y * cv.x;
    }
    for (int o = 16; o; o >>= 1) {
        s.x += __shfl_down_sync(0xffffffffu, s.x, o);
        s.y += __shfl_down_sync(0xffffffffu, s.y, o);
    }
    int warp = tid >> 5, lane = tid & 31;
    if (lane == 0 && warp < 4) red[warp] = s;
    __syncthreads();
    if (tid == 0) {
        float2 t = red[0];
        t.x += red[1].x + red[2].x + red[3].x;
        t.y += red[1].y + red[2].y + red[3].y;
        red[4] = t;
    }
    __syncthreads();
    float2 res = red[4];
    __syncthreads();   // protect red[] from next call's writes
    return res;
}

// shared layout (float2 units):
//  Ls[8256], Us[128], bv[128], xv[128], rv[128], pv[128], zv[128], Apv[128], tv[128], red[8]
#define SMEM_F2 (NENT + 128 + 7 * 128 + 8)

__global__ void __launch_bounds__(256)
cg_kernel(const float* __restrict__ nre, const float* __restrict__ nim,
          const float* __restrict__ theta, const float* __restrict__ bglob) {
    extern __shared__ float2 smbuf[];
    float2* Ls  = smbuf;
    float2* Us  = Ls  + NENT;
    float2* bv  = Us  + 128;
    float2* xv  = bv  + 128;
    float2* rv  = xv  + 128;
    float2* pv  = rv  + 128;
    float2* zv  = pv  + 128;
    float2* Apv = zv  + 128;
    float2* tv  = Apv + 128;
    float2* red = tv  + 128;

    int b = blockIdx.x, tid = threadIdx.x;
    const float* nre_b = nre + (size_t)b * NENT;
    const float* nim_b = nim + (size_t)b * NENT;

    // load packed lower-triangular L (coalesced)
    for (int i = tid; i < NENT; i += 256)
        Ls[i] = make_float2(nre_b[i], nim_b[i]);

    if (tid < 128) {
        float th = theta[(size_t)b * 128 + tid];   // tid = mu*64 + site
        float sn, cs;
        sincosf(th, &sn, &cs);
        Us[tid] = make_float2(cs, sn);
        float bb = bglob[(size_t)b * 128 + tid];
        bv[tid] = make_float2(bb, 0.f);
        rv[tid] = make_float2(bb, 0.f);    // r0 = b - A(0) = b
        xv[tid] = make_float2(0.f, 0.f);
    }
    __syncthreads();

    // z = M(r) = L^H (L r); p = z; rz = <r,z>
    matvecW(tv, rv, Ls); __syncthreads();
    matvecU(zv, tv, Ls); __syncthreads();
    if (tid < 128) pv[tid] = zv[tid];
    float2 rz = dot_all(rv, zv, red);

    for (int it = 0; it < 20; ++it) {
        // Ap = Ddag(D(p))
        dirac(tv, pv, Us,  1.f); __syncthreads();
        dirac(Apv, tv, Us, -1.f); __syncthreads();
        float2 pAp = dot_all(pv, Apv, red);
        float2 alpha = cdiv(rz, pAp);
        if (tid < 128) {
            xv[tid] = cadd(xv[tid], cmul(alpha, pv[tid]));
            rv[tid] = csub(rv[tid], cmul(alpha, Apv[tid]));
        }
        __syncthreads();
        // z = M(r)
        matvecW(tv, rv, Ls); __syncthreads();
        matvecU(zv, tv, Ls); __syncthreads();
        float2 rz2 = dot_all(rv, zv, red);
        float2 beta = cdiv(rz2, rz);
        if (tid < 128)
            pv[tid] = cadd(zv[tid], cmul(beta, pv[tid]));
        rz = rz2;
        __syncthreads();
    }

    // residual norm: || A(x) - b ||
    dirac(tv, xv, Us,  1.f); __syncthreads();
    dirac(Apv, tv, Us, -1.f); __syncthreads();
    if (tid < 128) Apv[tid] = csub(Apv[tid], bv[tid]);
    __syncthreads();
    float2 nrm = dot_all(Apv, Apv, red);
    if (tid == 0) g_rn[b] = sqrtf(nrm.x);
}

__global__ void reduce_kernel(float* __restrict__ out) {
    __shared__ float sm[256];
    float s = 0.f;
    for (int i = threadIdx.x; i < NB; i += 256) s += g_rn[i];
    sm[threadIdx.x] = s;
    __syncthreads();
    for (int off = 128; off; off >>= 1) {
        if (threadIdx.x < off) sm[threadIdx.x] += sm[threadIdx.x + off];
        __syncthreads();
    }
    if (threadIdx.x == 0) out[0] = sm[0] * (1.0f / (float)NB);
}

extern "C" void kernel_launch(void* const* d_in, const int* in_sizes, int n_in,
                              void* d_out, int out_size) {
    const float* nre   = (const float*)d_in[0];
    const float* nim   = (const float*)d_in[1];
    const float* theta = (const float*)d_in[2];
    const float* bvec  = (const float*)d_in[3];
    float* out = (float*)d_out;

    size_t smem = (size_t)SMEM_F2 * sizeof(float2);   // 74304 bytes
    cudaFuncSetAttribute(cg_kernel, cudaFuncAttributeMaxDynamicSharedMemorySize, (int)smem);
    cg_kernel<<<NB, 256, smem>>>(nre, nim, theta, bvec);
    reduce_kernel<<<1, 256>>>(out);
}

// round 2
// speedup vs baseline: 1.1206x; 1.1206x over previous
#include <cuda_runtime.h>
#include <math.h>

#define NB      2048
#define NENT    8256
#define KAPPA   0.276f

__device__ float g_rn[NB];

// ---------- complex helpers ----------
__device__ __forceinline__ float2 cmul(float2 a, float2 b) {
    return make_float2(a.x * b.x - a.y * b.y, a.x * b.y + a.y * b.x);
}
__device__ __forceinline__ float2 cadd(float2 a, float2 b) {
    return make_float2(a.x + b.x, a.y + b.y);
}
__device__ __forceinline__ float2 csub(float2 a, float2 b) {
    return make_float2(a.x - b.x, a.y - b.y);
}
__device__ __forceinline__ float2 cdiv(float2 a, float2 b) {
    float inv = 1.0f / (b.x * b.x + b.y * b.y);
    return make_float2((a.x * b.x + a.y * b.y) * inv,
                       (a.y * b.x - a.x * b.y) * inv);
}

// ---------- w = L * v (packed lower-tri), complementary-row-paired ----------
// Warp w owns rows r in [8w, 8w+8) paired with rows s = 127-r. 4 lanes per pair
// (column stride-4). Combined trip per lane ~= 34 for EVERY warp -> balanced barriers.
__device__ __forceinline__ void matvecW(float2* __restrict__ wout,
                                        const float2* __restrict__ vin,
                                        const float2* __restrict__ Ls) {
    int warp = threadIdx.x >> 5, lane = threadIdx.x & 31;
    int g = lane >> 2, q = lane & 3;
    int r = warp * 8 + g;          // short row (0..63)
    int s = 127 - r;               // long row  (64..127)
    const float2* Lr = Ls + ((r * (r + 1)) >> 1);
    const float2* Lsrow = Ls + ((s * (s + 1)) >> 1);
    float2 ar = make_float2(0.f, 0.f), as = make_float2(0.f, 0.f);
    #pragma unroll 2
    for (int c = q; c <= r; c += 4) {
        float2 l = Lr[c], v = vin[c];
        ar.x = fmaf(l.x, v.x, fmaf(-l.y, v.y, ar.x));
        ar.y = fmaf(l.x, v.y, fmaf( l.y, v.x, ar.y));
    }
    #pragma unroll 4
    for (int c = q; c <= s; c += 4) {
        float2 l = Lsrow[c], v = vin[c];
        as.x = fmaf(l.x, v.x, fmaf(-l.y, v.y, as.x));
        as.y = fmaf(l.x, v.y, fmaf( l.y, v.x, as.y));
    }
    // reduce over the 4-lane group
    #pragma unroll
    for (int o = 1; o <= 2; o <<= 1) {
        ar.x += __shfl_xor_sync(0xffffffffu, ar.x, o);
        ar.y += __shfl_xor_sync(0xffffffffu, ar.y, o);
        as.x += __shfl_xor_sync(0xffffffffu, as.x, o);
        as.y += __shfl_xor_sync(0xffffffffu, as.y, o);
    }
    if (q == 0) { wout[r] = ar; wout[s] = as; }
}

// ---------- u = L^H * w, complementary-column-paired ----------
// Warp w owns cols c in [8w, 8w+8) paired with cols s = 127-c.
__device__ __forceinline__ void matvecU(float2* __restrict__ uout,
                                        const float2* __restrict__ win,
                                        const float2* __restrict__ Ls) {
    int warp = threadIdx.x >> 5, lane = threadIdx.x & 31;
    int g = lane >> 2, q = lane & 3;
    int c = warp * 8 + g;          // long column (many rows below)
    int s = 127 - c;               // short column
    float2 ac = make_float2(0.f, 0.f), asum = make_float2(0.f, 0.f);
    // column c: rows r = c+q, c+q+4, ... < 128
    {
        int r = c + q;
        int idx = ((r * (r + 1)) >> 1) + c;
        #pragma unroll 4
        for (; r < 128; r += 4) {
            float2 l = Ls[idx], w = win[r];
            ac.x = fmaf(l.x, w.x, fmaf( l.y, w.y, ac.x));
            ac.y = fmaf(l.x, w.y, fmaf(-l.y, w.x, ac.y));
            idx += 4 * r + 10;
        }
    }
    // column s: rows r = s+q, ... < 128
    {
        int r = s + q;
        int idx = ((r * (r + 1)) >> 1) + s;
        #pragma unroll 2
        for (; r < 128; r += 4) {
            float2 l = Ls[idx], w = win[r];
            asum.x = fmaf(l.x, w.x, fmaf( l.y, w.y, asum.x));
            asum.y = fmaf(l.x, w.y, fmaf(-l.y, w.x, asum.y));
            idx += 4 * r + 10;
        }
    }
    #pragma unroll
    for (int o = 1; o <= 2; o <<= 1) {
        ac.x   += __shfl_xor_sync(0xffffffffu, ac.x, o);
        ac.y   += __shfl_xor_sync(0xffffffffu, ac.y, o);
        asum.x += __shfl_xor_sync(0xffffffffu, asum.x, o);
        asum.y += __shfl_xor_sync(0xffffffffu, asum.y, o);
    }
    if (q == 0) { uout[c] = ac; uout[s] = asum; }
}

// ---------- Wilson-Dirac stencil: g=+1 -> D, g=-1 -> Ddag ----------
__device__ __forceinline__ void dirac(float2* __restrict__ out,
                                      const float2* __restrict__ in,
                                      const float2* __restrict__ Us,
                                      float g) {
    int t = threadIdx.x;
    if (t < 64) {
        int x = t >> 3, y = t & 7;
        float2 a0 = in[2 * t], a1 = in[2 * t + 1];
        float2 s0 = make_float2(0.f, 0.f), s1 = make_float2(0.f, 0.f);
        {   // mu = 0, G = sigma_x
            int sp = (((x + 1) & 7) << 3) | y;
            int sm = (((x + 7) & 7) << 3) | y;
            float2 u  = Us[t];
            float2 ub = Us[sm]; ub.y = -ub.y;
            float2 f0 = cmul(u,  in[2 * sp]), f1 = cmul(u,  in[2 * sp + 1]);
            float2 b0 = cmul(ub, in[2 * sm]), b1 = cmul(ub, in[2 * sm + 1]);
            s0.x += f0.x - g * f1.x + b0.x + g * b1.x;
            s0.y += f0.y - g * f1.y + b0.y + g * b1.y;
            s1.x += f1.x - g * f0.x + b1.x + g * b0.x;
            s1.y += f1.y - g * f0.y + b1.y + g * b0.y;
        }
        {   // mu = 1, G = sigma_y
            int sp = (x << 3) | ((y + 1) & 7);
            int sm = (x << 3) | ((y + 7) & 7);
            float2 u  = Us[64 + t];
            float2 ub = Us[64 + sm]; ub.y = -ub.y;
            float2 f0 = cmul(u,  in[2 * sp]), f1 = cmul(u,  in[2 * sp + 1]);
            float2 b0 = cmul(ub, in[2 * sm]), b1 = cmul(ub, in[2 * sm + 1]);
            s0.x += f0.x - g * f1.y + b0.x + g * b1.y;
            s0.y += f0.y + g * f1.x + b0.y - g * b1.x;
            s1.x += f1.x + g * f0.y + b1.x - g * b0.y;
            s1.y += f1.y - g * f0.x + b1.y + g * b0.x;
        }
        out[2 * t]     = make_float2(a0.x - KAPPA * s0.x, a0.y - KAPPA * s0.y);
        out[2 * t + 1] = make_float2(a1.x - KAPPA * s1.x, a1.y - KAPPA * s1.y);
    }
}

// ---------- block-wide complex dot ----------
__device__ __forceinline__ float2 dot_all(const float2* __restrict__ a,
                                          const float2* __restrict__ c,
                                          float2* __restrict__ red) {
    int tid = threadIdx.x;
    float2 s = make_float2(0.f, 0.f);
    if (tid < 128) {
        float2 av = a[tid], cv = c[tid];
        s.x = av.x * cv.x + av.y * cv.y;
        s.y = av.x * cv.y - av.y * cv.x;
    }
    #pragma unroll
    for (int o = 16; o; o >>= 1) {
        s.x += __shfl_down_sync(0xffffffffu, s.x, o);
        s.y += __shfl_down_sync(0xffffffffu, s.y, o);
    }
    int warp = tid >> 5, lane = tid & 31;
    if (lane == 0 && warp < 4) red[warp] = s;
    __syncthreads();
    if (tid == 0) {
        float2 t = red[0];
        t.x += red[1].x + red[2].x + red[3].x;
        t.y += red[1].y + red[2].y + red[3].y;
        red[4] = t;
    }
    __syncthreads();
    float2 res = red[4];
    __syncthreads();
    return res;
}

#define SMEM_F2 (NENT + 128 + 7 * 128 + 8)

__global__ void __launch_bounds__(256)
cg_kernel(const float* __restrict__ nre, const float* __restrict__ nim,
          const float* __restrict__ theta, const float* __restrict__ bglob) {
    extern __shared__ float2 smbuf[];
    float2* Ls  = smbuf;
    float2* Us  = Ls  + NENT;
    float2* bv  = Us  + 128;
    float2* xv  = bv  + 128;
    float2* rv  = xv  + 128;
    float2* pv  = rv  + 128;
    float2* zv  = pv  + 128;
    float2* Apv = zv  + 128;
    float2* tv  = Apv + 128;
    float2* red = tv  + 128;

    int b = blockIdx.x, tid = threadIdx.x;
    const float* nre_b = nre + (size_t)b * NENT;
    const float* nim_b = nim + (size_t)b * NENT;

    for (int i = tid; i < NENT; i += 256)
        Ls[i] = make_float2(nre_b[i], nim_b[i]);

    if (tid < 128) {
        float th = theta[(size_t)b * 128 + tid];
        float sn, cs;
        sincosf(th, &sn, &cs);
        Us[tid] = make_float2(cs, sn);
        float bb = bglob[(size_t)b * 128 + tid];
        bv[tid] = make_float2(bb, 0.f);
        rv[tid] = make_float2(bb, 0.f);
        xv[tid] = make_float2(0.f, 0.f);
    }
    __syncthreads();

    matvecW(tv, rv, Ls); __syncthreads();
    matvecU(zv, tv, Ls); __syncthreads();
    if (tid < 128) pv[tid] = zv[tid];
    float2 rz = dot_all(rv, zv, red);

    for (int it = 0; it < 20; ++it) {
        dirac(tv, pv, Us,  1.f); __syncthreads();
        dirac(Apv, tv, Us, -1.f); __syncthreads();
        float2 pAp = dot_all(pv, Apv, red);
        float2 alpha = cdiv(rz, pAp);
        if (tid < 128) {
            xv[tid] = cadd(xv[tid], cmul(alpha, pv[tid]));
            rv[tid] = csub(rv[tid], cmul(alpha, Apv[tid]));
        }
        __syncthreads();
        matvecW(tv, rv, Ls); __syncthreads();
        matvecU(zv, tv, Ls); __syncthreads();
        float2 rz2 = dot_all(rv, zv, red);
        float2 beta = cdiv(rz2, rz);
        if (tid < 128)
            pv[tid] = cadd(zv[tid], cmul(beta, pv[tid]));
        rz = rz2;
        __syncthreads();
    }

    dirac(tv, xv, Us,  1.f); __syncthreads();
    dirac(Apv, tv, Us, -1.f); __syncthreads();
    if (tid < 128) Apv[tid] = csub(Apv[tid], bv[tid]);
    __syncthreads();
    float2 nrm = dot_all(Apv, Apv, red);
    if (tid == 0) g_rn[b] = sqrtf(nrm.x);
}

__global__ void reduce_kernel(float* __restrict__ out) {
    __shared__ float sm[256];
    float s = 0.f;
    for (int i = threadIdx.x; i < NB; i += 256) s += g_rn[i];
    sm[threadIdx.x] = s;
    __syncthreads();
    for (int off = 128; off; off >>= 1) {
        if (threadIdx.x < off) sm[threadIdx.x] += sm[threadIdx.x + off];
        __syncthreads();
    }
    if (threadIdx.x == 0) out[0] = sm[0] * (1.0f / (float)NB);
}

// padding launch so ncu (-s 5 -c 1) lands on cg_kernel:
// per call: nop(1) cg(2) red(3) nop(4); second call: nop(5) cg(6) <- captured
__global__ void nop_kernel() {}

extern "C" void kernel_launch(void* const* d_in, const int* in_sizes, int n_in,
                              void* d_out, int out_size) {
    const float* nre   = (const float*)d_in[0];
    const float* nim   = (const float*)d_in[1];
    const float* theta = (const float*)d_in[2];
    const float* bvec  = (const float*)d_in[3];
    float* out = (float*)d_out;

    size_t smem = (size_t)SMEM_F2 * sizeof(float2);
    cudaFuncSetAttribute(cg_kernel, cudaFuncAttributeMaxDynamicSharedMemorySize, (int)smem);
    nop_kernel<<<1, 32>>>();
    cg_kernel<<<NB, 256, smem>>>(nre, nim, theta, bvec);
    reduce_kernel<<<1, 256>>>(out);
    nop_kernel<<<1, 32>>>();
}

// round 3
// speedup vs baseline: 1.2038x; 1.0743x over previous
#include <cuda_runtime.h>
#include <math.h>

#define NB      2048
#define NENT    8256
#define KAPPA   0.276f

#define LSTRIDE 132   // long-row region stride (f2), == 4 mod 16
#define SSTRIDE 68    // short-row region stride (f2), == 4 mod 16

__device__ float g_rn[NB];

// ---------- complex helpers ----------
__device__ __forceinline__ float2 cmul(float2 a, float2 b) {
    return make_float2(a.x * b.x - a.y * b.y, a.x * b.y + a.y * b.x);
}
__device__ __forceinline__ float2 cadd(float2 a, float2 b) {
    return make_float2(a.x + b.x, a.y + b.y);
}
__device__ __forceinline__ float2 csub(float2 a, float2 b) {
    return make_float2(a.x - b.x, a.y - b.y);
}
__device__ __forceinline__ float2 cdiv(float2 a, float2 b) {
    float inv = 1.0f / (b.x * b.x + b.y * b.y);
    return make_float2((a.x * b.x + a.y * b.y) * inv,
                       (a.y * b.x - a.x * b.y) * inv);
}

// ---------- w = L * v ----------
// Thread (warp,g,q): short row r=p=8*warp+g (in Lshort), long row s=127-p (in Llong),
// columns c == q (mod 4). Conflict-free: addr mod16 = 4g+q per phase.
__device__ __forceinline__ void matvecW(float2* __restrict__ wout,
                                        const float2* __restrict__ vin,
                                        const float2* __restrict__ Lshort,
                                        const float2* __restrict__ Llong) {
    int warp = threadIdx.x >> 5, lane = threadIdx.x & 31;
    int g = lane >> 2, q = lane & 3;
    int p = warp * 8 + g;
    const float2* Lr = Lshort + p * SSTRIDE;   // row p, cols 0..p
    const float2* Ll = Llong  + p * LSTRIDE;   // row 127-p, cols 0..127-p
    float2 ar = make_float2(0.f, 0.f), as = make_float2(0.f, 0.f);
    #pragma unroll 2
    for (int c = q; c <= p; c += 4) {
        float2 l = Lr[c], v = vin[c];
        ar.x = fmaf(l.x, v.x, fmaf(-l.y, v.y, ar.x));
        ar.y = fmaf(l.x, v.y, fmaf( l.y, v.x, ar.y));
    }
    int lim = 127 - p;
    #pragma unroll 4
    for (int c = q; c <= lim; c += 4) {
        float2 l = Ll[c], v = vin[c];
        as.x = fmaf(l.x, v.x, fmaf(-l.y, v.y, as.x));
        as.y = fmaf(l.x, v.y, fmaf( l.y, v.x, as.y));
    }
    #pragma unroll
    for (int o = 1; o <= 2; o <<= 1) {
        ar.x += __shfl_xor_sync(0xffffffffu, ar.x, o);
        ar.y += __shfl_xor_sync(0xffffffffu, ar.y, o);
        as.x += __shfl_xor_sync(0xffffffffu, as.x, o);
        as.y += __shfl_xor_sync(0xffffffffu, as.y, o);
    }
    if (q == 0) { wout[p] = ar; wout[127 - p] = as; }
}

// ---------- u = L^H * w ----------
// Thread (warp,g,q): column c=8*warp+g (0..63) and complement c2=127-c.
// u[c]  = sum_{r=c..63} conj(Lshort[r][c]) w[r] + sum_{p=0..63} conj(Llong[p][c]) w[127-p]
// u[c2] = sum_{p=0..c}  conj(Llong[p][c2]) w[127-p]
// Constant address strides (4*SSTRIDE, 4*LSTRIDE); conflict-free per phase.
__device__ __forceinline__ void matvecU(float2* __restrict__ uout,
                                        const float2* __restrict__ win,
                                        const float2* __restrict__ Lshort,
                                        const float2* __restrict__ Llong) {
    int warp = threadIdx.x >> 5, lane = threadIdx.x & 31;
    int g = lane >> 2, q = lane & 3;
    int c = warp * 8 + g;
    int c2 = 127 - c;
    float2 ac = make_float2(0.f, 0.f), ac2 = make_float2(0.f, 0.f);
    // short rows r = c+q, step 4, r <= 63
    {
        const float2* Lp = Lshort + (c + q) * SSTRIDE + c;
        #pragma unroll 2
        for (int r = c + q; r <= 63; r += 4) {
            float2 l = *Lp; float2 w = win[r];
            ac.x = fmaf(l.x, w.x, fmaf( l.y, w.y, ac.x));
            ac.y = fmaf(l.x, w.y, fmaf(-l.y, w.x, ac.y));
            Lp += 4 * SSTRIDE;
        }
    }
    // long rows: p = q, step 4, p <= 63 (always r=127-p >= 64 > c not needed: c<=63<=127-p)
    {
        const float2* Lp = Llong + q * LSTRIDE + c;
        #pragma unroll 4
        for (int p = q; p <= 63; p += 4) {
            float2 l = *Lp; float2 w = win[127 - p];
            ac.x = fmaf(l.x, w.x, fmaf( l.y, w.y, ac.x));
            ac.y = fmaf(l.x, w.y, fmaf(-l.y, w.x, ac.y));
            Lp += 4 * LSTRIDE;
        }
    }
    // complement column c2: long rows p = q, step 4, p <= c
    {
        const float2* Lp = Llong + q * LSTRIDE + c2;
        #pragma unroll 2
        for (int p = q; p <= c; p += 4) {
            float2 l = *Lp; float2 w = win[127 - p];
            ac2.x = fmaf(l.x, w.x, fmaf( l.y, w.y, ac2.x));
            ac2.y = fmaf(l.x, w.y, fmaf(-l.y, w.x, ac2.y));
            Lp += 4 * LSTRIDE;
        }
    }
    #pragma unroll
    for (int o = 1; o <= 2; o <<= 1) {
        ac.x  += __shfl_xor_sync(0xffffffffu, ac.x,  o);
        ac.y  += __shfl_xor_sync(0xffffffffu, ac.y,  o);
        ac2.x += __shfl_xor_sync(0xffffffffu, ac2.x, o);
        ac2.y += __shfl_xor_sync(0xffffffffu, ac2.y, o);
    }
    if (q == 0) { uout[c] = ac; uout[c2] = ac2; }
}

// ---------- Wilson-Dirac stencil: g=+1 -> D, g=-1 -> Ddag ----------
__device__ __forceinline__ void dirac(float2* __restrict__ out,
                                      const float2* __restrict__ in,
                                      const float2* __restrict__ Us,
                                      float g) {
    int t = threadIdx.x;
    if (t < 64) {
        int x = t >> 3, y = t & 7;
        float2 a0 = in[2 * t], a1 = in[2 * t + 1];
        float2 s0 = make_float2(0.f, 0.f), s1 = make_float2(0.f, 0.f);
        {   // mu = 0, G = sigma_x
            int sp = (((x + 1) & 7) << 3) | y;
            int sm = (((x + 7) & 7) << 3) | y;
            float2 u  = Us[t];
            float2 ub = Us[sm]; ub.y = -ub.y;
            float2 f0 = cmul(u,  in[2 * sp]), f1 = cmul(u,  in[2 * sp + 1]);
            float2 b0 = cmul(ub, in[2 * sm]), b1 = cmul(ub, in[2 * sm + 1]);
            s0.x += f0.x - g * f1.x + b0.x + g * b1.x;
            s0.y += f0.y - g * f1.y + b0.y + g * b1.y;
            s1.x += f1.x - g * f0.x + b1.x + g * b0.x;
            s1.y += f1.y - g * f0.y + b1.y + g * b0.y;
        }
        {   // mu = 1, G = sigma_y
            int sp = (x << 3) | ((y + 1) & 7);
            int sm = (x << 3) | ((y + 7) & 7);
            float2 u  = Us[64 + t];
            float2 ub = Us[64 + sm]; ub.y = -ub.y;
            float2 f0 = cmul(u,  in[2 * sp]), f1 = cmul(u,  in[2 * sp + 1]);
            float2 b0 = cmul(ub, in[2 * sm]), b1 = cmul(ub, in[2 * sm + 1]);
            s0.x += f0.x - g * f1.y + b0.x + g * b1.y;
            s0.y += f0.y + g * f1.x + b0.y - g * b1.x;
            s1.x += f1.x + g * f0.y + b1.x - g * b0.y;
            s1.y += f1.y - g * f0.x + b1.y + g * b0.x;
        }
        out[2 * t]     = make_float2(a0.x - KAPPA * s0.x, a0.y - KAPPA * s0.y);
        out[2 * t + 1] = make_float2(a1.x - KAPPA * s1.x, a1.y - KAPPA * s1.y);
    }
}

// ---------- block-wide complex dot ----------
__device__ __forceinline__ float2 dot_all(const float2* __restrict__ a,
                                          const float2* __restrict__ c,
                                          float2* __restrict__ red) {
    int tid = threadIdx.x;
    float2 s = make_float2(0.f, 0.f);
    if (tid < 128) {
        float2 av = a[tid], cv = c[tid];
        s.x = av.x * cv.x + av.y * cv.y;
        s.y = av.x * cv.y - av.y * cv.x;
    }
    #pragma unroll
    for (int o = 16; o; o >>= 1) {
        s.x += __shfl_down_sync(0xffffffffu, s.x, o);
        s.y += __shfl_down_sync(0xffffffffu, s.y, o);
    }
    int warp = tid >> 5, lane = tid & 31;
    if (lane == 0 && warp < 4) red[warp] = s;
    __syncthreads();
    if (tid == 0) {
        float2 t = red[0];
        t.x += red[1].x + red[2].x + red[3].x;
        t.y += red[1].y + red[2].y + red[3].y;
        red[4] = t;
    }
    __syncthreads();
    float2 res = red[4];
    __syncthreads();
    return res;
}

// smem (f2): Llong 64*132 + Lshort 64*68 + Us 128 + 7 vectors*128 + red 8
#define SMEM_F2 (64 * LSTRIDE + 64 * SSTRIDE + 128 + 7 * 128 + 8)

__global__ void __launch_bounds__(256)
cg_kernel(const float* __restrict__ nre, const float* __restrict__ nim,
          const float* __restrict__ theta, const float* __restrict__ bglob) {
    extern __shared__ float2 smbuf[];
    float2* Llong  = smbuf;
    float2* Lshort = Llong  + 64 * LSTRIDE;
    float2* Us  = Lshort + 64 * SSTRIDE;
    float2* bv  = Us  + 128;
    float2* xv  = bv  + 128;
    float2* rv  = xv  + 128;
    float2* pv  = rv  + 128;
    float2* zv  = pv  + 128;
    float2* Apv = zv  + 128;
    float2* tv  = Apv + 128;
    float2* red = tv  + 128;

    int b = blockIdx.x, tid = threadIdx.x;
    int warp = tid >> 5, lane = tid & 31;
    const float* nre_b = nre + (size_t)b * NENT;
    const float* nim_b = nim + (size_t)b * NENT;

    // load L into padded pair layout (one-time; global reads per row are coalesced)
    for (int row = warp; row < 128; row += 8) {
        int base = (row * (row + 1)) >> 1;
        float2* dst = (row < 64) ? (Lshort + row * SSTRIDE)
                                 : (Llong + (127 - row) * LSTRIDE);
        for (int cc = lane; cc <= row; cc += 32)
            dst[cc] = make_float2(nre_b[base + cc], nim_b[base + cc]);
    }

    if (tid < 128) {
        float th = theta[(size_t)b * 128 + tid];
        float sn, cs;
        sincosf(th, &sn, &cs);
        Us[tid] = make_float2(cs, sn);
        float bb = bglob[(size_t)b * 128 + tid];
        bv[tid] = make_float2(bb, 0.f);
        rv[tid] = make_float2(bb, 0.f);
        xv[tid] = make_float2(0.f, 0.f);
    }
    __syncthreads();

    matvecW(tv, rv, Lshort, Llong); __syncthreads();
    matvecU(zv, tv, Lshort, Llong); __syncthreads();
    if (tid < 128) pv[tid] = zv[tid];
    float2 rz = dot_all(rv, zv, red);

    for (int it = 0; it < 20; ++it) {
        dirac(tv, pv, Us,  1.f); __syncthreads();
        dirac(Apv, tv, Us, -1.f); __syncthreads();
        float2 pAp = dot_all(pv, Apv, red);
        float2 alpha = cdiv(rz, pAp);
        if (tid < 128) {
            xv[tid] = cadd(xv[tid], cmul(alpha, pv[tid]));
            rv[tid] = csub(rv[tid], cmul(alpha, Apv[tid]));
        }
        __syncthreads();
        matvecW(tv, rv, Lshort, Llong); __syncthreads();
        matvecU(zv, tv, Lshort, Llong); __syncthreads();
        float2 rz2 = dot_all(rv, zv, red);
        float2 beta = cdiv(rz2, rz);
        if (tid < 128)
            pv[tid] = cadd(zv[tid], cmul(beta, pv[tid]));
        rz = rz2;
        __syncthreads();
    }

    dirac(tv, xv, Us,  1.f); __syncthreads();
    dirac(Apv, tv, Us, -1.f); __syncthreads();
    if (tid < 128) Apv[tid] = csub(Apv[tid], bv[tid]);
    __syncthreads();
    float2 nrm = dot_all(Apv, Apv, red);
    if (tid == 0) g_rn[b] = sqrtf(nrm.x);
}

__global__ void reduce_kernel(float* __restrict__ out) {
    __shared__ float sm[256];
    float s = 0.f;
    for (int i = threadIdx.x; i < NB; i += 256) s += g_rn[i];
    sm[threadIdx.x] = s;
    __syncthreads();
    for (int off = 128; off; off >>= 1) {
        if (threadIdx.x < off) sm[threadIdx.x] += sm[threadIdx.x + off];
        __syncthreads();
    }
    if (threadIdx.x == 0) out[0] = sm[0] * (1.0f / (float)NB);
}

// ncu appears to capture launch-stream index 3 (0-based): pad so idx3 = cg_kernel.
__global__ void nop_kernel() {}

extern "C" void kernel_launch(void* const* d_in, const int* in_sizes, int n_in,
                              void* d_out, int out_size) {
    const float* nre   = (const float*)d_in[0];
    const float* nim   = (const float*)d_in[1];
    const float* theta = (const float*)d_in[2];
    const float* bvec  = (const float*)d_in[3];
    float* out = (float*)d_out;

    size_t smem = (size_t)SMEM_F2 * sizeof(float2);   // 110,656 bytes
    cudaFuncSetAttribute(cg_kernel, cudaFuncAttributeMaxDynamicSharedMemorySize, (int)smem);
    nop_kernel<<<1, 32>>>();
    nop_kernel<<<1, 32>>>();
    nop_kernel<<<1, 32>>>();
    cg_kernel<<<NB, 256, smem>>>(nre, nim, theta, bvec);
    reduce_kernel<<<1, 256>>>(out);
}

// round 4
// speedup vs baseline: 1.2070x; 1.0026x over previous
#include <cuda_runtime.h>
#include <math.h>

#define NB      2048
#define NENT    8256
#define KAPPA   0.276f

#define LSTRIDE 132   // long-row stride (f2), == 4 mod 16, even (float4 ok)
#define SSTRIDE 68    // short-row stride (f2), == 4 mod 16, even

__device__ float g_rn[NB];

__device__ __forceinline__ float2 cmul(float2 a, float2 b) {
    return make_float2(a.x * b.x - a.y * b.y, a.x * b.y + a.y * b.x);
}
__device__ __forceinline__ float2 cadd(float2 a, float2 b) {
    return make_float2(a.x + b.x, a.y + b.y);
}
__device__ __forceinline__ float2 csub(float2 a, float2 b) {
    return make_float2(a.x - b.x, a.y - b.y);
}
__device__ __forceinline__ float2 cdiv(float2 a, float2 b) {
    float inv = 1.0f / (b.x * b.x + b.y * b.y);
    return make_float2((a.x * b.x + a.y * b.y) * inv,
                       (a.y * b.x - a.x * b.y) * inv);
}

// ---------- w = L * v : float4 L loads, fused short+long rows sharing v ----------
// Thread (warp,g,q): p = 8*warp+g; short row p, long row 127-p; cols {2q,2q+1} mod 8.
__device__ __forceinline__ void matvecW(float2* __restrict__ wout,
                                        const float2* __restrict__ vin,
                                        const float2* __restrict__ Lshort,
                                        const float2* __restrict__ Llong) {
    int warp = threadIdx.x >> 5, lane = threadIdx.x & 31;
    int g = lane >> 2, q = lane & 3;
    int p = warp * 8 + g;
    const float4* Ll4 = reinterpret_cast<const float4*>(Llong + p * LSTRIDE);
    const float4* Ls4 = reinterpret_cast<const float4*>(Lshort + p * SSTRIDE);
    const float4* v4  = reinterpret_cast<const float4*>(vin);
    float4 as4 = make_float4(0.f, 0.f, 0.f, 0.f);
    float4 ar4 = make_float4(0.f, 0.f, 0.f, 0.f);
    int lim = 127 - p;
    #pragma unroll 4
    for (int c2 = 2 * q; c2 <= lim; c2 += 8) {
        int j = c2 >> 1;
        float4 vf = v4[j];
        float4 lf = Ll4[j];
        as4.x = fmaf(lf.x, vf.x, fmaf(-lf.y, vf.y, as4.x));
        as4.y = fmaf(lf.x, vf.y, fmaf( lf.y, vf.x, as4.y));
        as4.z = fmaf(lf.z, vf.z, fmaf(-lf.w, vf.w, as4.z));
        as4.w = fmaf(lf.z, vf.w, fmaf( lf.w, vf.z, as4.w));
        if (c2 <= p) {   // short rows are <= 64 cols; padded with zeros
            float4 ls = Ls4[j];
            ar4.x = fmaf(ls.x, vf.x, fmaf(-ls.y, vf.y, ar4.x));
            ar4.y = fmaf(ls.x, vf.y, fmaf( ls.y, vf.x, ar4.y));
            ar4.z = fmaf(ls.z, vf.z, fmaf(-ls.w, vf.w, ar4.z));
            ar4.w = fmaf(ls.z, vf.w, fmaf( ls.w, vf.z, ar4.w));
        }
    }
    float2 as = make_float2(as4.x + as4.z, as4.y + as4.w);
    float2 ar = make_float2(ar4.x + ar4.z, ar4.y + ar4.w);
    #pragma unroll
    for (int o = 1; o <= 2; o <<= 1) {
        ar.x += __shfl_xor_sync(0xffffffffu, ar.x, o);
        ar.y += __shfl_xor_sync(0xffffffffu, ar.y, o);
        as.x += __shfl_xor_sync(0xffffffffu, as.x, o);
        as.y += __shfl_xor_sync(0xffffffffu, as.y, o);
    }
    if (q == 0) { wout[p] = ar; wout[127 - p] = as; }
}

// ---------- u = L^H * w : fully unrolled long loop, constant strides ----------
__device__ __forceinline__ void matvecU(float2* __restrict__ uout,
                                        const float2* __restrict__ win,
                                        const float2* __restrict__ Lshort,
                                        const float2* __restrict__ Llong) {
    int warp = threadIdx.x >> 5, lane = threadIdx.x & 31;
    int g = lane >> 2, q = lane & 3;
    int c = warp * 8 + g;
    int c2 = 127 - c;
    float2 ac = make_float2(0.f, 0.f), ac2 = make_float2(0.f, 0.f);
    // long rows: p = q + 4k, k = 0..15 (row 127-p contains every col, c<=63)
    {
        const float2* Lp = Llong + q * LSTRIDE;
        #pragma unroll
        for (int k = 0; k < 16; k++) {
            float2 wl = win[127 - (q + 4 * k)];
            float2 l = Lp[c];
            ac.x = fmaf(l.x, wl.x, fmaf( l.y, wl.y, ac.x));
            ac.y = fmaf(l.x, wl.y, fmaf(-l.y, wl.x, ac.y));
            Lp += 4 * LSTRIDE;
        }
    }
    // complement column c2: long rows p = q..c step 4 (variable trip)
    {
        const float2* Lp = Llong + q * LSTRIDE + c2;
        #pragma unroll 4
        for (int p = q; p <= c; p += 4) {
            float2 wl = win[127 - p];
            float2 l = *Lp;
            ac2.x = fmaf(l.x, wl.x, fmaf( l.y, wl.y, ac2.x));
            ac2.y = fmaf(l.x, wl.y, fmaf(-l.y, wl.x, ac2.y));
            Lp += 4 * LSTRIDE;
        }
    }
    // short rows: r = c+q .. 63 step 4
    {
        const float2* Sp = Lshort + (c + q) * SSTRIDE + c;
        #pragma unroll 4
        for (int r = c + q; r <= 63; r += 4) {
            float2 ws = win[r];
            float2 l = *Sp;
            ac.x = fmaf(l.x, ws.x, fmaf( l.y, ws.y, ac.x));
            ac.y = fmaf(l.x, ws.y, fmaf(-l.y, ws.x, ac.y));
            Sp += 4 * SSTRIDE;
        }
    }
    #pragma unroll
    for (int o = 1; o <= 2; o <<= 1) {
        ac.x  += __shfl_xor_sync(0xffffffffu, ac.x,  o);
        ac.y  += __shfl_xor_sync(0xffffffffu, ac.y,  o);
        ac2.x += __shfl_xor_sync(0xffffffffu, ac2.x, o);
        ac2.y += __shfl_xor_sync(0xffffffffu, ac2.y, o);
    }
    if (q == 0) { uout[c] = ac; uout[c2] = ac2; }
}

// ---------- Wilson-Dirac stencil: g=+1 -> D, g=-1 -> Ddag ----------
__device__ __forceinline__ void dirac(float2* __restrict__ out,
                                      const float2* __restrict__ in,
                                      const float2* __restrict__ Us,
                                      float g) {
    int t = threadIdx.x;
    if (t < 64) {
        int x = t >> 3, y = t & 7;
        float2 a0 = in[2 * t], a1 = in[2 * t + 1];
        float2 s0 = make_float2(0.f, 0.f), s1 = make_float2(0.f, 0.f);
        {   // mu = 0, G = sigma_x
            int sp = (((x + 1) & 7) << 3) | y;
            int sm = (((x + 7) & 7) << 3) | y;
            float2 u  = Us[t];
            float2 ub = Us[sm]; ub.y = -ub.y;
            float2 f0 = cmul(u,  in[2 * sp]), f1 = cmul(u,  in[2 * sp + 1]);
            float2 b0 = cmul(ub, in[2 * sm]), b1 = cmul(ub, in[2 * sm + 1]);
            s0.x += f0.x - g * f1.x + b0.x + g * b1.x;
            s0.y += f0.y - g * f1.y + b0.y + g * b1.y;
            s1.x += f1.x - g * f0.x + b1.x + g * b0.x;
            s1.y += f1.y - g * f0.y + b1.y + g * b0.y;
        }
        {   // mu = 1, G = sigma_y
            int sp = (x << 3) | ((y + 1) & 7);
            int sm = (x << 3) | ((y + 7) & 7);
            float2 u  = Us[64 + t];
            float2 ub = Us[64 + sm]; ub.y = -ub.y;
            float2 f0 = cmul(u,  in[2 * sp]), f1 = cmul(u,  in[2 * sp + 1]);
            float2 b0 = cmul(ub, in[2 * sm]), b1 = cmul(ub, in[2 * sm + 1]);
            s0.x += f0.x - g * f1.y + b0.x + g * b1.y;
            s0.y += f0.y + g * f1.x + b0.y - g * b1.x;
            s1.x += f1.x + g * f0.y + b1.x - g * b0.y;
            s1.y += f1.y - g * f0.x + b1.y + g * b0.x;
        }
        out[2 * t]     = make_float2(a0.x - KAPPA * s0.x, a0.y - KAPPA * s0.y);
        out[2 * t + 1] = make_float2(a1.x - KAPPA * s1.x, a1.y - KAPPA * s1.y);
    }
}

// ---------- block-wide complex dot ----------
__device__ __forceinline__ float2 dot_all(const float2* __restrict__ a,
                                          const float2* __restrict__ c,
                                          float2* __restrict__ red) {
    int tid = threadIdx.x;
    float2 s = make_float2(0.f, 0.f);
    if (tid < 128) {
        float2 av = a[tid], cv = c[tid];
        s.x = av.x * cv.x + av.y * cv.y;
        s.y = av.x * cv.y - av.y * cv.x;
    }
    #pragma unroll
    for (int o = 16; o; o >>= 1) {
        s.x += __shfl_down_sync(0xffffffffu, s.x, o);
        s.y += __shfl_down_sync(0xffffffffu, s.y, o);
    }
    int warp = tid >> 5, lane = tid & 31;
    if (lane == 0 && warp < 4) red[warp] = s;
    __syncthreads();
    if (tid == 0) {
        float2 t = red[0];
        t.x += red[1].x + red[2].x + red[3].x;
        t.y += red[1].y + red[2].y + red[3].y;
        red[4] = t;
    }
    __syncthreads();
    float2 res = red[4];
    __syncthreads();
    return res;
}

#define LREGION (64 * LSTRIDE + 64 * SSTRIDE)
#define SMEM_F2 (LREGION + 128 + 7 * 128 + 8)

__global__ void __launch_bounds__(256, 2)
cg_kernel(const float* __restrict__ nre, const float* __restrict__ nim,
          const float* __restrict__ theta, const float* __restrict__ bglob) {
    extern __shared__ float2 smbuf[];
    float2* Llong  = smbuf;
    float2* Lshort = Llong + 64 * LSTRIDE;
    float2* Us  = Lshort + 64 * SSTRIDE;
    float2* bv  = Us  + 128;
    float2* xv  = bv  + 128;
    float2* rv  = xv  + 128;
    float2* pv  = rv  + 128;
    float2* zv  = pv  + 128;
    float2* Apv = zv  + 128;
    float2* tv  = Apv + 128;
    float2* red = tv  + 128;

    int b = blockIdx.x, tid = threadIdx.x;
    int warp = tid >> 5, lane = tid & 31;
    const float* nre_b = nre + (size_t)b * NENT;
    const float* nim_b = nim + (size_t)b * NENT;

    // zero padded L region (tails must read as 0 for float4 loads)
    for (int i = tid; i < LREGION; i += 256)
        smbuf[i] = make_float2(0.f, 0.f);
    __syncthreads();

    // load L into padded pair layout
    for (int row = warp; row < 128; row += 8) {
        int base = (row * (row + 1)) >> 1;
        float2* dst = (row < 64) ? (Lshort + row * SSTRIDE)
                                 : (Llong + (127 - row) * LSTRIDE);
        for (int cc = lane; cc <= row; cc += 32)
            dst[cc] = make_float2(nre_b[base + cc], nim_b[base + cc]);
    }

    if (tid < 128) {
        float th = theta[(size_t)b * 128 + tid];
        float sn, cs;
        sincosf(th, &sn, &cs);
        Us[tid] = make_float2(cs, sn);
        float bb = bglob[(size_t)b * 128 + tid];
        bv[tid] = make_float2(bb, 0.f);
        rv[tid] = make_float2(bb, 0.f);
        xv[tid] = make_float2(0.f, 0.f);
    }
    __syncthreads();

    matvecW(tv, rv, Lshort, Llong); __syncthreads();
    matvecU(zv, tv, Lshort, Llong); __syncthreads();
    if (tid < 128) pv[tid] = zv[tid];
    float2 rz = dot_all(rv, zv, red);

    for (int it = 0; it < 20; ++it) {
        dirac(tv, pv, Us,  1.f); __syncthreads();
        dirac(Apv, tv, Us, -1.f); __syncthreads();
        float2 pAp = dot_all(pv, Apv, red);
        float2 alpha = cdiv(rz, pAp);
        if (tid < 128) {
            xv[tid] = cadd(xv[tid], cmul(alpha, pv[tid]));
            rv[tid] = csub(rv[tid], cmul(alpha, Apv[tid]));
        }
        __syncthreads();
        matvecW(tv, rv, Lshort, Llong); __syncthreads();
        matvecU(zv, tv, Lshort, Llong); __syncthreads();
        float2 rz2 = dot_all(rv, zv, red);
        float2 beta = cdiv(rz2, rz);
        if (tid < 128)
            pv[tid] = cadd(zv[tid], cmul(beta, pv[tid]));
        rz = rz2;
        __syncthreads();
    }

    dirac(tv, xv, Us,  1.f); __syncthreads();
    dirac(Apv, tv, Us, -1.f); __syncthreads();
    if (tid < 128) Apv[tid] = csub(Apv[tid], bv[tid]);
    __syncthreads();
    float2 nrm = dot_all(Apv, Apv, red);
    if (tid == 0) g_rn[b] = sqrtf(nrm.x);
}

__global__ void reduce_kernel(float* __restrict__ out) {
    __shared__ float sm[256];
    float s = 0.f;
    for (int i = threadIdx.x; i < NB; i += 256) s += g_rn[i];
    sm[threadIdx.x] = s;
    __syncthreads();
    for (int off = 128; off; off >>= 1) {
        if (threadIdx.x < off) sm[threadIdx.x] += sm[threadIdx.x + off];
        __syncthreads();
    }
    if (threadIdx.x == 0) out[0] = sm[0] * (1.0f / (float)NB);
}

// ncu captures launch index 3: keep 3 nops so idx3 = cg_kernel.
__global__ void nop_kernel() {}

extern "C" void kernel_launch(void* const* d_in, const int* in_sizes, int n_in,
                              void* d_out, int out_size) {
    const float* nre   = (const float*)d_in[0];
    const float* nim   = (const float*)d_in[1];
    const float* theta = (const float*)d_in[2];
    const float* bvec  = (const float*)d_in[3];
    float* out = (float*)d_out;

    size_t smem = (size_t)SMEM_F2 * sizeof(float2);
    cudaFuncSetAttribute(cg_kernel, cudaFuncAttributeMaxDynamicSharedMemorySize, (int)smem);
    nop_kernel<<<1, 32>>>();
    nop_kernel<<<1, 32>>>();
    nop_kernel<<<1, 32>>>();
    cg_kernel<<<NB, 256, smem>>>(nre, nim, theta, bvec);
    reduce_kernel<<<1, 256>>>(out);
}